// round 15
// baseline (speedup 1.0000x reference)
#include <cuda_runtime.h>
#include <cstdint>

// Problem constants
constexpr int B_   = 16;
constexpr int NH   = 64;
constexpr int NW   = 64;
constexpr int DO   = 768;
constexpr int KH   = 16;
constexpr int KW   = 16;
constexpr int H_   = 512;
constexpr int WF   = 512;

constexpr int M_ = B_ * NH * NW;   // 65536
constexpr int N_ = KH * KW;        // 256
constexpr int K_ = DO;             // 768

// GEMM tiling
constexpr int BM = 128, BN = 128, BK = 32;
constexpr int NTILES = K_ / BK;    // 24
constexpr int APAD   = 36;
constexpr int STAGES = 2;
constexpr int MAT_FLOATS   = 128 * APAD;
constexpr int STAGE_FLOATS = 2 * MAT_FLOATS;
constexpr int SMEM_BYTES   = STAGES * STAGE_FLOATS * 4;   // 73728 -> 3 CTAs/SM

// 64 MB scratch: proj[m][n], m = ((b*64+h)*64+w), n = dh*16+dw
__device__ float g_proj[(size_t)M_ * N_];
// W pre-converted to tf32 (rna) once per launch
__device__ float g_wt[(size_t)N_ * K_];

__device__ __forceinline__ uint32_t f2tf32(float x) {
    uint32_t r;
    asm volatile("cvt.rna.tf32.f32 %0, %1;" : "=r"(r) : "f"(x));
    return r;
}
__device__ __forceinline__ uint32_t smem_u32(const void* p) {
    uint32_t a;
    asm("{ .reg .u64 t; cvta.to.shared.u64 t, %1; cvt.u32.u64 %0, t; }"
        : "=r"(a) : "l"(p));
    return a;
}
__device__ __forceinline__ void cpa16(uint32_t s, const void* g) {
    asm volatile("cp.async.cg.shared.global [%0], [%1], 16;" :: "r"(s), "l"(g));
}

#define MMA_TF32(d, a, b)                                                         \
    asm volatile(                                                                 \
        "mma.sync.aligned.m16n8k8.row.col.f32.tf32.tf32.f32 "                     \
        "{%0,%1,%2,%3}, {%4,%5,%6,%7}, {%8,%9}, {%0,%1,%2,%3};\n"                 \
        : "+f"(d[0]), "+f"(d[1]), "+f"(d[2]), "+f"(d[3])                          \
        : "r"(a[0]), "r"(a[1]), "r"(a[2]), "r"(a[3]), "r"(b[0]), "r"(b[1]))

// ---------------- W pre-convert: fp32 -> tf32(rna) bits ----------------
__global__ __launch_bounds__(256) void wconv_kernel(const float* __restrict__ W) {
    const int i = (blockIdx.x * blockDim.x + threadIdx.x) * 4;   // N_*K_ = 196608
    float4 v = *(const float4*)(W + i);
    uint4 o;
    o.x = f2tf32(v.x); o.y = f2tf32(v.y); o.z = f2tf32(v.z); o.w = f2tf32(v.w);
    *(uint4*)(g_wt + i) = o;
}

// proj = tgt[M,K] @ W[N,K]^T ; A fed raw fp32 (HW tf32 truncation), W pre-rounded
// 2-stage double buffer, 3 CTAs/SM target.
__global__ __launch_bounds__(256, 3) void gemm_tf32_kernel(const float* __restrict__ A) {
    extern __shared__ float smem[];
    const uint32_t sb = smem_u32(smem);

    const int tid  = threadIdx.x;
    const int bN   = blockIdx.x * BN;
    const int bM   = blockIdx.y * BM;

    const int warp = tid >> 5;
    const int lane = tid & 31;
    const int wM   = (warp & 1) * 64;
    const int wN   = (warp >> 1) * 32;
    const int grp  = lane >> 2;
    const int tig  = lane & 3;

    auto issue_stage = [&](int t, int slot) {
        const int k0 = t * BK;
        const uint32_t as = sb + (uint32_t)(slot * STAGE_FLOATS) * 4;
        const uint32_t bs = as + (uint32_t)MAT_FLOATS * 4;
        #pragma unroll
        for (int p = 0; p < 4; ++p) {
            const int idx = p * 256 + tid;
            const int row = idx >> 3, ch = idx & 7;
            cpa16(as + (uint32_t)(row * APAD + ch * 4) * 4,
                  A + (size_t)(bM + row) * K_ + k0 + ch * 4);
        }
        #pragma unroll
        for (int p = 0; p < 4; ++p) {
            const int idx = p * 256 + tid;
            const int row = idx >> 3, ch = idx & 7;
            cpa16(bs + (uint32_t)(row * APAD + ch * 4) * 4,
                  g_wt + (size_t)(bN + row) * K_ + k0 + ch * 4);
        }
        asm volatile("cp.async.commit_group;" ::: "memory");
    };

    float acc[4][4][4];
    #pragma unroll
    for (int i = 0; i < 4; ++i)
        #pragma unroll
        for (int j = 0; j < 4; ++j)
            #pragma unroll
            for (int r = 0; r < 4; ++r) acc[i][j][r] = 0.f;

    issue_stage(0, 0);

    for (int t = 0; t < NTILES; ++t) {
        __syncthreads();   // all warps done reading slot (t+1)&1 from iter t-1
        if (t + 1 < NTILES) {
            issue_stage(t + 1, (t + 1) & 1);
            asm volatile("cp.async.wait_group %0;" :: "n"(1) : "memory");
        } else {
            asm volatile("cp.async.wait_group %0;" :: "n"(0) : "memory");
        }
        __syncthreads();   // stage t visible to all

        const float* as = smem + (t & 1) * STAGE_FLOATS;
        const float* bs = as + MAT_FLOATS;
        #pragma unroll
        for (int kk = 0; kk < 4; ++kk) {
            const int k0 = kk * 8;
            uint32_t af[4][4], bf[4][2];
            #pragma unroll
            for (int i = 0; i < 4; ++i) {
                const float* p0 = as + (wM + i * 16 + grp) * APAD + k0 + tig;
                af[i][0] = __float_as_uint(p0[0]);      // raw fp32: HW tf32 truncation
                af[i][2] = __float_as_uint(p0[4]);
                const float* p1 = p0 + 8 * APAD;
                af[i][1] = __float_as_uint(p1[0]);
                af[i][3] = __float_as_uint(p1[4]);
            }
            #pragma unroll
            for (int j = 0; j < 4; ++j) {
                const float* p0 = bs + (wN + j * 8 + grp) * APAD + k0 + tig;
                bf[j][0] = __float_as_uint(p0[0]);      // already tf32(rna)
                bf[j][1] = __float_as_uint(p0[4]);
            }
            #pragma unroll
            for (int i = 0; i < 4; ++i)
                #pragma unroll
                for (int j = 0; j < 4; ++j)
                    MMA_TF32(acc[i][j], af[i], bf[j]);
        }
    }

    // epilogue: contiguous [m][n] stores (fully coalesced)
    #pragma unroll
    for (int i = 0; i < 4; ++i) {
        const int r0 = bM + wM + i * 16 + grp;
        #pragma unroll
        for (int j = 0; j < 4; ++j) {
            const int c0 = bN + wN + j * 8 + tig * 2;
            *(float2*)(g_proj + (size_t)r0 * N_ + c0) =
                make_float2(acc[i][j][0], acc[i][j][1]);
            *(float2*)(g_proj + (size_t)(r0 + 8) * N_ + c0) =
                make_float2(acc[i][j][2], acc[i][j][3]);
        }
    }
}

// ---------------- fold main: one thread per 2 pixels (edges fixed later) -------
__global__ __launch_bounds__(256) void fold_main_kernel(float* __restrict__ out) {
    const int t   = blockIdx.x * blockDim.x + threadIdx.x;   // 2,097,152 threads
    const int b   = t >> 17;
    const int rem = t & 131071;
    const int y   = rem >> 8;
    const int xq  = rem & 255;
    const int x0  = xq << 1;

    const int Y  = y >> 3,  py = y & 7;
    const int X  = x0 >> 3, px = x0 & 7;

    const float* base =
        g_proj + (((size_t)((b << 6 | Y) << 6 | X)) << 8) + py * 16 + px;

    const bool hasX = (X > 0), hasY = (Y > 0);

    float2 s = *(const float2*)base;
    if (hasX) {
        float2 v = *(const float2*)(base - 248);
        s.x += v.x; s.y += v.y;
    }
    if (hasY) {
        const float* pu = base - 16384 + 128;
        float2 v = *(const float2*)pu;
        s.x += v.x; s.y += v.y;
        if (hasX) {
            float2 w = *(const float2*)(pu - 248);
            s.x += w.x; s.y += w.y;
        }
    }
    const float inv = 1.0f / (float)((hasX ? 2 : 1) * (hasY ? 2 : 1));
    s.x *= inv; s.y *= inv;
    *(float2*)(out + ((size_t)b << 18) + (y << 9) + x0) = s;
}

// ---------------- fold edge: one WARP per edge pixel, formula-indexed ----------
__device__ __forceinline__ void contrib(int c, int i, int& cell, int& off) {
    if (c == 511) {
        cell = (i == 1) ? 62 : 63;
        off  = (i == 0) ? 7 : (i == 1) ? 15 : (i + 6);
    } else {
        cell = (c >> 3) - (i != 0 ? 1 : 0);
        off  = (c & 7) + (i != 0 ? 8 : 0);
    }
}
__device__ __forceinline__ int contrib_cnt(int c) {
    return (c == 511) ? 10 : ((c >> 3) > 0 ? 2 : 1);
}

__global__ __launch_bounds__(256) void fold_edge_kernel(float* __restrict__ out) {
    const int gw   = (blockIdx.x * blockDim.x + threadIdx.x) >> 5;  // 16384 warps
    const int lane = threadIdx.x & 31;
    const int b = gw >> 10;
    const int r = gw & 1023;
    int y, x;
    if (r < 512) { y = H_ - 1; x = r; }
    else         { y = r - 512; x = WF - 1; }

    const int cy = contrib_cnt(y);
    const int cx = contrib_cnt(x);
    const int total = cy * cx;                 // <= 100

    const float* pb = g_proj + ((size_t)b << 20);
    float s = 0.f;
    for (int idx = lane; idx < total; idx += 32) {
        const int i = idx / cx, j = idx - i * cx;
        int hy, dy, hx, dx;
        contrib(y, i, hy, dy);
        contrib(x, j, hx, dx);
        s += pb[((size_t)(hy * 64 + hx) << 8) + dy * 16 + dx];
    }
    #pragma unroll
    for (int o = 16; o > 0; o >>= 1)
        s += __shfl_xor_sync(0xFFFFFFFFu, s, o);

    if (lane == 0)
        out[((size_t)b << 18) + (y << 9) + x] = s / (float)total;
}

extern "C" void kernel_launch(void* const* d_in, const int* in_sizes, int n_in,
                              void* d_out, int out_size) {
    const float* tgt    = (const float*)d_in[0];   // [16, 4096, 768]
    const float* weight = (const float*)d_in[1];   // [256, 768]
    float* out = (float*)d_out;                    // [16, 512, 512]

    // W -> tf32(rna) once
    wconv_kernel<<<(N_ * K_ / 4) / 256, 256>>>(weight);

    cudaFuncSetAttribute(gemm_tf32_kernel,
                         cudaFuncAttributeMaxDynamicSharedMemorySize, SMEM_BYTES);

    dim3 grid(N_ / BN, M_ / BM);   // (2, 512)
    gemm_tf32_kernel<<<grid, 256, SMEM_BYTES>>>(tgt);

    const int main_threads = B_ * H_ * (WF / 2);   // 2,097,152
    fold_main_kernel<<<main_threads / 256, 256>>>(out);

    fold_edge_kernel<<<2048, 256>>>(out);
}

// round 16
// speedup vs baseline: 1.1351x; 1.1351x over previous
#include <cuda_runtime.h>
#include <cstdint>

// Problem constants
constexpr int B_   = 16;
constexpr int NH   = 64;
constexpr int NW   = 64;
constexpr int DO   = 768;
constexpr int KH   = 16;
constexpr int KW   = 16;
constexpr int H_   = 512;
constexpr int WF   = 512;

constexpr int M_ = B_ * NH * NW;   // 65536
constexpr int N_ = KH * KW;        // 256
constexpr int K_ = DO;             // 768

// GEMM tiling: BM x BN = 128 x 64, 8 warps of 32x32 -> 32 acc floats/thread
constexpr int BM = 128, BN = 64, BK = 32;
constexpr int NTILES = K_ / BK;    // 24
constexpr int APAD   = 36;
constexpr int STAGES = 2;
constexpr int A_FLOATS = BM * APAD;            // 4608
constexpr int B_FLOATS = BN * APAD;            // 2304
constexpr int STAGE_FLOATS = A_FLOATS + B_FLOATS;
constexpr int SMEM_BYTES   = STAGES * STAGE_FLOATS * 4;   // 55296 -> 3+ CTAs by smem

// 64 MB scratch: proj[m][n], m = ((b*64+h)*64+w), n = dh*16+dw
__device__ float g_proj[(size_t)M_ * N_];
// W pre-converted to tf32 (rna) once per launch
__device__ float g_wt[(size_t)N_ * K_];

__device__ __forceinline__ uint32_t f2tf32(float x) {
    uint32_t r;
    asm volatile("cvt.rna.tf32.f32 %0, %1;" : "=r"(r) : "f"(x));
    return r;
}
__device__ __forceinline__ uint32_t smem_u32(const void* p) {
    uint32_t a;
    asm("{ .reg .u64 t; cvta.to.shared.u64 t, %1; cvt.u32.u64 %0, t; }"
        : "=r"(a) : "l"(p));
    return a;
}
__device__ __forceinline__ void cpa16(uint32_t s, const void* g) {
    asm volatile("cp.async.cg.shared.global [%0], [%1], 16;" :: "r"(s), "l"(g));
}

#define MMA_TF32(d, a, b)                                                         \
    asm volatile(                                                                 \
        "mma.sync.aligned.m16n8k8.row.col.f32.tf32.tf32.f32 "                     \
        "{%0,%1,%2,%3}, {%4,%5,%6,%7}, {%8,%9}, {%0,%1,%2,%3};\n"                 \
        : "+f"(d[0]), "+f"(d[1]), "+f"(d[2]), "+f"(d[3])                          \
        : "r"(a[0]), "r"(a[1]), "r"(a[2]), "r"(a[3]), "r"(b[0]), "r"(b[1]))

// ---------------- W pre-convert: fp32 -> tf32(rna) bits ----------------
__global__ __launch_bounds__(256) void wconv_kernel(const float* __restrict__ W) {
    const int i = (blockIdx.x * blockDim.x + threadIdx.x) * 4;   // N_*K_ = 196608
    float4 v = *(const float4*)(W + i);
    uint4 o;
    o.x = f2tf32(v.x); o.y = f2tf32(v.y); o.z = f2tf32(v.z); o.w = f2tf32(v.w);
    *(uint4*)(g_wt + i) = o;
}

// proj = tgt[M,K] @ W[N,K]^T ; A raw fp32 (HW tf32 truncation), W pre-rounded.
// 2-stage double buffer; 3 CTAs/SM (32 acc floats -> ~72 natural regs < 85 cap).
__global__ __launch_bounds__(256, 3) void gemm_tf32_kernel(const float* __restrict__ A) {
    extern __shared__ float smem[];
    const uint32_t sb = smem_u32(smem);

    const int tid  = threadIdx.x;
    const int bN   = blockIdx.x * BN;
    const int bM   = blockIdx.y * BM;

    const int warp = tid >> 5;
    const int lane = tid & 31;
    const int wM   = (warp >> 1) * 32;     // 4 warps along M
    const int wN   = (warp & 1) * 32;      // 2 warps along N
    const int grp  = lane >> 2;
    const int tig  = lane & 3;

    auto issue_stage = [&](int t, int slot) {
        const int k0 = t * BK;
        const uint32_t as = sb + (uint32_t)(slot * STAGE_FLOATS) * 4;
        const uint32_t bs = as + (uint32_t)A_FLOATS * 4;
        #pragma unroll
        for (int p = 0; p < 4; ++p) {          // A: 1024 chunks
            const int idx = p * 256 + tid;
            const int row = idx >> 3, ch = idx & 7;
            cpa16(as + (uint32_t)(row * APAD + ch * 4) * 4,
                  A + (size_t)(bM + row) * K_ + k0 + ch * 4);
        }
        #pragma unroll
        for (int p = 0; p < 2; ++p) {          // B: 512 chunks
            const int idx = p * 256 + tid;
            const int row = idx >> 3, ch = idx & 7;
            cpa16(bs + (uint32_t)(row * APAD + ch * 4) * 4,
                  g_wt + (size_t)(bN + row) * K_ + k0 + ch * 4);
        }
        asm volatile("cp.async.commit_group;" ::: "memory");
    };

    float acc[2][4][4];
    #pragma unroll
    for (int i = 0; i < 2; ++i)
        #pragma unroll
        for (int j = 0; j < 4; ++j)
            #pragma unroll
            for (int r = 0; r < 4; ++r) acc[i][j][r] = 0.f;

    issue_stage(0, 0);

    for (int t = 0; t < NTILES; ++t) {
        __syncthreads();
        if (t + 1 < NTILES) {
            issue_stage(t + 1, (t + 1) & 1);
            asm volatile("cp.async.wait_group %0;" :: "n"(1) : "memory");
        } else {
            asm volatile("cp.async.wait_group %0;" :: "n"(0) : "memory");
        }
        __syncthreads();

        const float* as = smem + (t & 1) * STAGE_FLOATS;
        const float* bs = as + A_FLOATS;
        #pragma unroll
        for (int kk = 0; kk < 4; ++kk) {
            const int k0 = kk * 8;
            uint32_t af[2][4], bf[4][2];
            #pragma unroll
            for (int i = 0; i < 2; ++i) {
                const float* p0 = as + (wM + i * 16 + grp) * APAD + k0 + tig;
                af[i][0] = __float_as_uint(p0[0]);      // raw fp32 -> HW tf32 trunc
                af[i][2] = __float_as_uint(p0[4]);
                const float* p1 = p0 + 8 * APAD;
                af[i][1] = __float_as_uint(p1[0]);
                af[i][3] = __float_as_uint(p1[4]);
            }
            #pragma unroll
            for (int j = 0; j < 4; ++j) {
                const float* p0 = bs + (wN + j * 8 + grp) * APAD + k0 + tig;
                bf[j][0] = __float_as_uint(p0[0]);      // already tf32(rna)
                bf[j][1] = __float_as_uint(p0[4]);
            }
            #pragma unroll
            for (int i = 0; i < 2; ++i)
                #pragma unroll
                for (int j = 0; j < 4; ++j)
                    MMA_TF32(acc[i][j], af[i], bf[j]);
        }
    }

    // epilogue: contiguous [m][n] stores (fully coalesced)
    #pragma unroll
    for (int i = 0; i < 2; ++i) {
        const int r0 = bM + wM + i * 16 + grp;
        #pragma unroll
        for (int j = 0; j < 4; ++j) {
            const int c0 = bN + wN + j * 8 + tig * 2;
            *(float2*)(g_proj + (size_t)r0 * N_ + c0) =
                make_float2(acc[i][j][0], acc[i][j][1]);
            *(float2*)(g_proj + (size_t)(r0 + 8) * N_ + c0) =
                make_float2(acc[i][j][2], acc[i][j][3]);
        }
    }
}

// ---------------- fold main: one thread per 2 pixels (edges fixed later) -------
__global__ __launch_bounds__(256) void fold_main_kernel(float* __restrict__ out) {
    const int t   = blockIdx.x * blockDim.x + threadIdx.x;   // 2,097,152 threads
    const int b   = t >> 17;
    const int rem = t & 131071;
    const int y   = rem >> 8;
    const int xq  = rem & 255;
    const int x0  = xq << 1;

    const int Y  = y >> 3,  py = y & 7;
    const int X  = x0 >> 3, px = x0 & 7;

    const float* base =
        g_proj + (((size_t)((b << 6 | Y) << 6 | X)) << 8) + py * 16 + px;

    const bool hasX = (X > 0), hasY = (Y > 0);

    float2 s = *(const float2*)base;
    if (hasX) {
        float2 v = *(const float2*)(base - 248);
        s.x += v.x; s.y += v.y;
    }
    if (hasY) {
        const float* pu = base - 16384 + 128;
        float2 v = *(const float2*)pu;
        s.x += v.x; s.y += v.y;
        if (hasX) {
            float2 w = *(const float2*)(pu - 248);
            s.x += w.x; s.y += w.y;
        }
    }
    const float inv = 1.0f / (float)((hasX ? 2 : 1) * (hasY ? 2 : 1));
    s.x *= inv; s.y *= inv;
    *(float2*)(out + ((size_t)b << 18) + (y << 9) + x0) = s;
}

// ---------------- fold edge: one WARP per edge pixel, formula-indexed ----------
__device__ __forceinline__ void contrib(int c, int i, int& cell, int& off) {
    if (c == 511) {
        cell = (i == 1) ? 62 : 63;
        off  = (i == 0) ? 7 : (i == 1) ? 15 : (i + 6);
    } else {
        cell = (c >> 3) - (i != 0 ? 1 : 0);
        off  = (c & 7) + (i != 0 ? 8 : 0);
    }
}
__device__ __forceinline__ int contrib_cnt(int c) {
    return (c == 511) ? 10 : ((c >> 3) > 0 ? 2 : 1);
}

__global__ __launch_bounds__(256) void fold_edge_kernel(float* __restrict__ out) {
    const int gw   = (blockIdx.x * blockDim.x + threadIdx.x) >> 5;  // 16384 warps
    const int lane = threadIdx.x & 31;
    const int b = gw >> 10;
    const int r = gw & 1023;
    int y, x;
    if (r < 512) { y = H_ - 1; x = r; }
    else         { y = r - 512; x = WF - 1; }

    const int cy = contrib_cnt(y);
    const int cx = contrib_cnt(x);
    const int total = cy * cx;                 // <= 100

    const float* pb = g_proj + ((size_t)b << 20);
    float s = 0.f;
    for (int idx = lane; idx < total; idx += 32) {
        const int i = idx / cx, j = idx - i * cx;
        int hy, dy, hx, dx;
        contrib(y, i, hy, dy);
        contrib(x, j, hx, dx);
        s += pb[((size_t)(hy * 64 + hx) << 8) + dy * 16 + dx];
    }
    #pragma unroll
    for (int o = 16; o > 0; o >>= 1)
        s += __shfl_xor_sync(0xFFFFFFFFu, s, o);

    if (lane == 0)
        out[((size_t)b << 18) + (y << 9) + x] = s / (float)total;
}

extern "C" void kernel_launch(void* const* d_in, const int* in_sizes, int n_in,
                              void* d_out, int out_size) {
    const float* tgt    = (const float*)d_in[0];   // [16, 4096, 768]
    const float* weight = (const float*)d_in[1];   // [256, 768]
    float* out = (float*)d_out;                    // [16, 512, 512]

    // W -> tf32(rna) once
    wconv_kernel<<<(N_ * K_ / 4) / 256, 256>>>(weight);

    cudaFuncSetAttribute(gemm_tf32_kernel,
                         cudaFuncAttributeMaxDynamicSharedMemorySize, SMEM_BYTES);

    dim3 grid(N_ / BN, M_ / BM);   // (4, 512): N fastest for A-tile L2 reuse
    gemm_tf32_kernel<<<grid, 256, SMEM_BYTES>>>(tgt);

    const int main_threads = B_ * H_ * (WF / 2);   // 2,097,152
    fold_main_kernel<<<main_threads / 256, 256>>>(out);

    fold_edge_kernel<<<2048, 256>>>(out);
}

// round 17
// speedup vs baseline: 1.9108x; 1.6833x over previous
#include <cuda_runtime.h>
#include <cstdint>

// Problem constants
constexpr int B_   = 16;
constexpr int NH   = 64;
constexpr int NW   = 64;
constexpr int DO   = 768;
constexpr int KH   = 16;
constexpr int KW   = 16;
constexpr int H_   = 512;
constexpr int WF   = 512;

constexpr int M_ = B_ * NH * NW;   // 65536
constexpr int N_ = KH * KW;        // 256
constexpr int K_ = DO;             // 768

// GEMM tiling (R14 known-good: 162 us)
constexpr int BM = 128, BN = 128, BK = 32;
constexpr int NTILES = K_ / BK;    // 24
constexpr int APAD   = 36;
constexpr int STAGES = 3;
constexpr int MAT_FLOATS   = 128 * APAD;
constexpr int STAGE_FLOATS = 2 * MAT_FLOATS;
constexpr int SMEM_BYTES   = STAGES * STAGE_FLOATS * 4;   // 110592

// 64 MB scratch: proj[m][n], m = ((b*64+h)*64+w), n = dh*16+dw
__device__ float g_proj[(size_t)M_ * N_];
// W pre-converted to tf32 (rna) once per launch
__device__ float g_wt[(size_t)N_ * K_];

__device__ __forceinline__ uint32_t f2tf32(float x) {
    uint32_t r;
    asm volatile("cvt.rna.tf32.f32 %0, %1;" : "=r"(r) : "f"(x));
    return r;
}
__device__ __forceinline__ uint32_t smem_u32(const void* p) {
    uint32_t a;
    asm("{ .reg .u64 t; cvta.to.shared.u64 t, %1; cvt.u32.u64 %0, t; }"
        : "=r"(a) : "l"(p));
    return a;
}
__device__ __forceinline__ void cpa16(uint32_t s, const void* g) {
    asm volatile("cp.async.cg.shared.global [%0], [%1], 16;" :: "r"(s), "l"(g));
}

#define MMA_TF32(d, a, b)                                                         \
    asm volatile(                                                                 \
        "mma.sync.aligned.m16n8k8.row.col.f32.tf32.tf32.f32 "                     \
        "{%0,%1,%2,%3}, {%4,%5,%6,%7}, {%8,%9}, {%0,%1,%2,%3};\n"                 \
        : "+f"(d[0]), "+f"(d[1]), "+f"(d[2]), "+f"(d[3])                          \
        : "r"(a[0]), "r"(a[1]), "r"(a[2]), "r"(a[3]), "r"(b[0]), "r"(b[1]))

// ---------------- W pre-convert: fp32 -> tf32(rna) bits ----------------
__global__ __launch_bounds__(256) void wconv_kernel(const float* __restrict__ W) {
    const int i = blockIdx.x * blockDim.x + threadIdx.x;   // 196608 threads
    ((uint32_t*)g_wt)[i] = f2tf32(W[i]);
}

// proj = tgt[M,K] @ W[N,K]^T ; A raw fp32 (HW tf32 truncation), W pre-rounded.
// 3-stage cp.async pipeline (R14 configuration).
__global__ __launch_bounds__(256) void gemm_tf32_kernel(const float* __restrict__ A) {
    extern __shared__ float smem[];
    const uint32_t sb = smem_u32(smem);

    const int tid  = threadIdx.x;
    const int bN   = blockIdx.x * BN;
    const int bM   = blockIdx.y * BM;

    const int warp = tid >> 5;
    const int lane = tid & 31;
    const int wM   = (warp & 1) * 64;
    const int wN   = (warp >> 1) * 32;
    const int grp  = lane >> 2;
    const int tig  = lane & 3;

    auto issue_stage = [&](int t, int slot) {
        const int k0 = t * BK;
        const uint32_t as = sb + (uint32_t)(slot * STAGE_FLOATS) * 4;
        const uint32_t bs = as + (uint32_t)MAT_FLOATS * 4;
        #pragma unroll
        for (int p = 0; p < 4; ++p) {
            const int idx = p * 256 + tid;
            const int row = idx >> 3, ch = idx & 7;
            cpa16(as + (uint32_t)(row * APAD + ch * 4) * 4,
                  A + (size_t)(bM + row) * K_ + k0 + ch * 4);
        }
        #pragma unroll
        for (int p = 0; p < 4; ++p) {
            const int idx = p * 256 + tid;
            const int row = idx >> 3, ch = idx & 7;
            cpa16(bs + (uint32_t)(row * APAD + ch * 4) * 4,
                  g_wt + (size_t)(bN + row) * K_ + k0 + ch * 4);
        }
        asm volatile("cp.async.commit_group;" ::: "memory");
    };

    float acc[4][4][4];
    #pragma unroll
    for (int i = 0; i < 4; ++i)
        #pragma unroll
        for (int j = 0; j < 4; ++j)
            #pragma unroll
            for (int r = 0; r < 4; ++r) acc[i][j][r] = 0.f;

    issue_stage(0, 0);
    issue_stage(1, 1);

    for (int t = 0; t < NTILES; ++t) {
        asm volatile("cp.async.wait_group %0;" :: "n"(1) : "memory");
        __syncthreads();
        if (t + 2 < NTILES) issue_stage(t + 2, (t + 2) % STAGES);

        const int slot = t % STAGES;
        const float* as = smem + slot * STAGE_FLOATS;
        const float* bs = as + MAT_FLOATS;
        #pragma unroll
        for (int kk = 0; kk < 4; ++kk) {
            const int k0 = kk * 8;
            uint32_t af[4][4], bf[4][2];
            #pragma unroll
            for (int i = 0; i < 4; ++i) {
                const float* p0 = as + (wM + i * 16 + grp) * APAD + k0 + tig;
                af[i][0] = __float_as_uint(p0[0]);      // raw fp32 -> HW tf32 trunc
                af[i][2] = __float_as_uint(p0[4]);
                const float* p1 = p0 + 8 * APAD;
                af[i][1] = __float_as_uint(p1[0]);
                af[i][3] = __float_as_uint(p1[4]);
            }
            #pragma unroll
            for (int j = 0; j < 4; ++j) {
                const float* p0 = bs + (wN + j * 8 + grp) * APAD + k0 + tig;
                bf[j][0] = __float_as_uint(p0[0]);      // already tf32(rna)
                bf[j][1] = __float_as_uint(p0[4]);
            }
            #pragma unroll
            for (int i = 0; i < 4; ++i)
                #pragma unroll
                for (int j = 0; j < 4; ++j)
                    MMA_TF32(acc[i][j], af[i], bf[j]);
        }
    }

    // epilogue: contiguous [m][n] stores (fully coalesced)
    #pragma unroll
    for (int i = 0; i < 4; ++i) {
        const int r0 = bM + wM + i * 16 + grp;
        #pragma unroll
        for (int j = 0; j < 4; ++j) {
            const int c0 = bN + wN + j * 8 + tig * 2;
            *(float2*)(g_proj + (size_t)r0 * N_ + c0) =
                make_float2(acc[i][j][0], acc[i][j][1]);
            *(float2*)(g_proj + (size_t)(r0 + 8) * N_ + c0) =
                make_float2(acc[i][j][2], acc[i][j][3]);
        }
    }
}

// ---------------- fused fold: main blocks + edge blocks in one launch ----------
constexpr int MAIN_BLOCKS = B_ * H_ * (WF / 2) / 256;   // 8192
constexpr int EDGE_BLOCKS = 2048;                        // 16384 warps, 1/edge pixel

// contribution i for coordinate c (array-free):
//   c == 511: i=0 -> (63, 7); i=1 -> (62, 15); i>=2 -> (63, i+6)   [count 10]
//   else    : i=0 -> (c>>3, c&7); i=1 -> (c>>3 - 1, (c&7)+8)       [count 2 or 1]
__device__ __forceinline__ void contrib(int c, int i, int& cell, int& off) {
    if (c == 511) {
        cell = (i == 1) ? 62 : 63;
        off  = (i == 0) ? 7 : (i == 1) ? 15 : (i + 6);
    } else {
        cell = (c >> 3) - (i != 0 ? 1 : 0);
        off  = (c & 7) + (i != 0 ? 8 : 0);
    }
}
__device__ __forceinline__ int contrib_cnt(int c) {
    return (c == 511) ? 10 : ((c >> 3) > 0 ? 2 : 1);
}

__global__ __launch_bounds__(256) void fold_kernel(float* __restrict__ out) {
    if (blockIdx.x < MAIN_BLOCKS) {
        // ---- main: one thread per 2 pixels; edge pixels NOT written here ----
        const int t   = blockIdx.x * blockDim.x + threadIdx.x;
        const int b   = t >> 17;
        const int rem = t & 131071;
        const int y   = rem >> 8;
        const int xq  = rem & 255;
        const int x0  = xq << 1;

        const int Y  = y >> 3,  py = y & 7;
        const int X  = x0 >> 3, px = x0 & 7;

        const float* base =
            g_proj + (((size_t)((b << 6 | Y) << 6 | X)) << 8) + py * 16 + px;

        const bool hasX = (X > 0), hasY = (Y > 0);

        float2 s = *(const float2*)base;
        if (hasX) {
            float2 v = *(const float2*)(base - 248);
            s.x += v.x; s.y += v.y;
        }
        if (hasY) {
            const float* pu = base - 16384 + 128;
            float2 v = *(const float2*)pu;
            s.x += v.x; s.y += v.y;
            if (hasX) {
                float2 w = *(const float2*)(pu - 248);
                s.x += w.x; s.y += w.y;
            }
        }
        const float inv = 1.0f / (float)((hasX ? 2 : 1) * (hasY ? 2 : 1));
        s.x *= inv; s.y *= inv;

        float* op = out + ((size_t)b << 18) + (y << 9) + x0;
        if (y != H_ - 1) {                 // y==511 row handled by edge blocks
            if (xq != 255) *(float2*)op = s;
            else           *op = s.x;      // x==511 handled by edge blocks
        }
    } else {
        // ---- edge: one warp per edge pixel (y==511 row, x==511 column) ----
        const int gw   = (blockIdx.x - MAIN_BLOCKS) * 8 + (threadIdx.x >> 5);
        const int lane = threadIdx.x & 31;
        const int b = gw >> 10;
        const int r = gw & 1023;
        int y, x;
        if (r < 512) { y = H_ - 1; x = r; }        // last row
        else         { y = r - 512; x = WF - 1; }  // last column (corner twice, same value)

        const int cy = contrib_cnt(y);
        const int cx = contrib_cnt(x);
        const int total = cy * cx;                 // <= 100

        const float* pb = g_proj + ((size_t)b << 20);
        float s = 0.f;
        for (int idx = lane; idx < total; idx += 32) {
            const int i = idx / cx, j = idx - i * cx;
            int hy, dy, hx, dx;
            contrib(y, i, hy, dy);
            contrib(x, j, hx, dx);
            s += pb[((size_t)(hy * 64 + hx) << 8) + dy * 16 + dx];
        }
        #pragma unroll
        for (int o = 16; o > 0; o >>= 1)
            s += __shfl_xor_sync(0xFFFFFFFFu, s, o);

        if (lane == 0)
            out[((size_t)b << 18) + (y << 9) + x] = s / (float)total;
    }
}

extern "C" void kernel_launch(void* const* d_in, const int* in_sizes, int n_in,
                              void* d_out, int out_size) {
    const float* tgt    = (const float*)d_in[0];   // [16, 4096, 768]
    const float* weight = (const float*)d_in[1];   // [256, 768]
    float* out = (float*)d_out;                    // [16, 512, 512]

    // W -> tf32(rna) once
    wconv_kernel<<<(N_ * K_) / 256, 256>>>(weight);

    cudaFuncSetAttribute(gemm_tf32_kernel,
                         cudaFuncAttributeMaxDynamicSharedMemorySize, SMEM_BYTES);

    dim3 grid(N_ / BN, M_ / BM);   // (2, 512)
    gemm_tf32_kernel<<<grid, 256, SMEM_BYTES>>>(tgt);

    fold_kernel<<<MAIN_BLOCKS + EDGE_BLOCKS, 256>>>(out);
}